// round 4
// baseline (speedup 1.0000x reference)
#include <cuda_runtime.h>
#include <cstdint>

// GausSplatingHead: per-point 3D Gaussian covariance from (scale, quaternion).
// R4: 512-point tiles, 2 points/thread, TMA bulk store for the output tile.
//   - rots:   direct dense float4 LDG (no smem round trip)
//   - scales: LDG float4 -> smem, read stride-3 (conflict-free)
//   - out:    STS.64 x6 per thread into smem, then ONE cp.async.bulk
//             (12 KB smem -> gmem) per block. No LDS/STG read-back phase.

#define TPB  256
#define TILE 512   // points per block

__device__ __forceinline__ uint32_t smem_u32(const void* p) {
    uint32_t a;
    asm("{ .reg .u64 t; cvta.to.shared.u64 t, %1; cvt.u32.u64 %0, t; }"
        : "=r"(a) : "l"(p));
    return a;
}

__device__ __forceinline__ void cov_from_q(
    float r, float x, float y, float z,
    float s0, float s1, float s2, float* o /*6*/)
{
    float n2 = r * r + x * x + y * y + z * z;
    // R(q/||q||) entries are quadratic in q: fold the normalization into the
    // factor 2 -> ss = 2/||q||^2. Algebraically identical to the reference.
    float ss = __fdividef(2.0f, n2);

    float xx = x * x * ss, yy = y * y * ss, zz = z * z * ss;
    float xy = x * y * ss, xz = x * z * ss, yz = y * z * ss;
    float rx = r * x * ss, ry = r * y * ss, rz = r * z * ss;

    float R00 = 1.0f - yy - zz, R01 = xy - rz, R02 = xz + ry;
    float R10 = xy + rz, R11 = 1.0f - xx - zz, R12 = yz - rx;
    float R20 = xz - ry, R21 = yz + rx, R22 = 1.0f - xx - yy;

    float a = s0 * s0, b = s1 * s1, c = s2 * s2;

    o[0] = R00 * R00 * a + R01 * R01 * b + R02 * R02 * c;  // 00
    o[1] = R00 * R10 * a + R01 * R11 * b + R02 * R12 * c;  // 01
    o[2] = R00 * R20 * a + R01 * R21 * b + R02 * R22 * c;  // 02
    o[3] = R10 * R10 * a + R11 * R11 * b + R12 * R12 * c;  // 11
    o[4] = R10 * R20 * a + R11 * R21 * b + R12 * R22 * c;  // 12
    o[5] = R20 * R20 * a + R21 * R21 * b + R22 * R22 * c;  // 22
}

__global__ __launch_bounds__(TPB) void gs_cov_tma_kernel(
    const float4* __restrict__ scales4,  // [n*3/4]
    const float4* __restrict__ rots4,    // [n]
    float4* __restrict__ out4,           // [n*6/4]
    int n)
{
    __shared__ float s_scales[TILE * 3];                 // 6 KB
    __shared__ __align__(16) float s_out[TILE * 6];      // 12 KB

    const int tid  = threadIdx.x;
    const int base = blockIdx.x * TILE;

    if (base + TILE <= n) {
        // ---- phase 1: all global loads issued up front ----
        size_t sbase = (size_t)base * 3 / 4;             // float4 index
        float4 q0 = rots4[base + tid];                    // point tid
        float4 q1 = rots4[base + TPB + tid];              // point tid+256
        float4 sc0 = scales4[sbase + tid];
        float4 sc1 = (tid < 128) ? scales4[sbase + TPB + tid]
                                 : make_float4(0, 0, 0, 0);

        ((float4*)s_scales)[tid] = sc0;
        if (tid < 128) ((float4*)s_scales)[TPB + tid] = sc1;
        __syncthreads();

        // ---- phase 2: compute 2 points, write outputs as float2 STS ----
        float o0[6], o1[6];
        cov_from_q(q0.x, q0.y, q0.z, q0.w,
                   s_scales[3 * tid + 0], s_scales[3 * tid + 1],
                   s_scales[3 * tid + 2], o0);
        {
            int p = TPB + tid;
            cov_from_q(q1.x, q1.y, q1.z, q1.w,
                       s_scales[3 * p + 0], s_scales[3 * p + 1],
                       s_scales[3 * p + 2], o1);
        }

        float2* so2 = (float2*)s_out;
        so2[3 * tid + 0]         = make_float2(o0[0], o0[1]);
        so2[3 * tid + 1]         = make_float2(o0[2], o0[3]);
        so2[3 * tid + 2]         = make_float2(o0[4], o0[5]);
        so2[3 * (TPB + tid) + 0] = make_float2(o1[0], o1[1]);
        so2[3 * (TPB + tid) + 1] = make_float2(o1[2], o1[3]);
        so2[3 * (TPB + tid) + 2] = make_float2(o1[4], o1[5]);
        __syncthreads();

        // ---- phase 3: one TMA bulk store, smem tile -> gmem ----
        if (tid == 0) {
            asm volatile("fence.proxy.async.shared::cta;" ::: "memory");
            const float* gdst = (const float*)out4 + (size_t)base * 6;
            uint32_t saddr = smem_u32(s_out);
            asm volatile(
                "cp.async.bulk.global.shared::cta.bulk_group [%0], [%1], %2;"
                :: "l"(gdst), "r"(saddr), "n"(TILE * 6 * 4)
                : "memory");
            asm volatile("cp.async.bulk.commit_group;" ::: "memory");
            asm volatile("cp.async.bulk.wait_group 0;" ::: "memory");
        }
    } else {
        // ---- tail tile (rare): scalar global path ----
        const float* scales = (const float*)scales4;
        const float* rots   = (const float*)rots4;
        float* out          = (float*)out4;
#pragma unroll
        for (int p = 0; p < 2; p++) {
            int i = base + p * TPB + tid;
            if (i < n) {
                float o[6];
                cov_from_q(rots[4 * i + 0], rots[4 * i + 1],
                           rots[4 * i + 2], rots[4 * i + 3],
                           scales[3 * i + 0], scales[3 * i + 1],
                           scales[3 * i + 2], o);
#pragma unroll
                for (int k = 0; k < 6; k++) out[6 * i + k] = o[k];
            }
        }
    }
}

extern "C" void kernel_launch(void* const* d_in, const int* in_sizes, int n_in,
                              void* d_out, int out_size)
{
    const float4* scales = (const float4*)d_in[0];  // [N,3]
    const float4* rots   = (const float4*)d_in[1];  // [N,4]
    float4* out          = (float4*)d_out;          // [N,6]

    int n = in_sizes[0] / 3;
    int blocks = (n + TILE - 1) / TILE;
    gs_cov_tma_kernel<<<blocks, TPB>>>(scales, rots, out, n);
}